// round 10
// baseline (speedup 1.0000x reference)
#include <cuda_runtime.h>
#include <cuda_fp16.h>

#define T_TOK  4096
#define DMODEL 1024
#define DFF    4096
#define NEXP   8
#define NSLOT  (T_TOK * 2)

#define BM 128
#define BN 128
#define BK 32                       // K elems per chunk
#define ROWB 80                     // padded row pitch bytes (64B data + 16B pad)
#define MATB (128 * ROWB)           // 10240 bytes per matrix
#define OFF_A 0
#define OFF_B MATB
#define STAGE_BYTES (2 * MATB)      // 20480
#define NSTAGE 4
#define SMEM_TOTAL (NSTAGE * STAGE_BYTES)   // 81920 >= epilogue 67584
#define EPITCH 132                  // fp32 epilogue row pitch (words)

// ---------------------------------------------------------------------------
// Scratch
// ---------------------------------------------------------------------------
__device__ int   g_cnt[NEXP];
__device__ int   g_list[NEXP][T_TOK];
__device__ float g_wt[NEXP][T_TOK];
__device__ __half g_x_h[(size_t)T_TOK * DMODEL];
__device__ __half g_w1_h[(size_t)NEXP * DFF * DMODEL];   // transposed [e][f][d]
__device__ __half g_w2_h[(size_t)NEXP * DMODEL * DFF];   // transposed [e][d][f]
__device__ __half g_h_h[(size_t)NSLOT * DFF];
__device__ float g_y[(size_t)NSLOT * DMODEL];

// ---------------------------------------------------------------------------
// PTX helpers (sm_80-class PTX only; tcgen05 rejected on plain sm_103 target)
// ---------------------------------------------------------------------------
__device__ __forceinline__ unsigned smem_u32(const void* p) {
    unsigned a;
    asm("{ .reg .u64 t; cvta.to.shared.u64 t, %1; cvt.u32.u64 %0, t; }"
        : "=r"(a) : "l"(p));
    return a;
}
__device__ __forceinline__ void cp16(unsigned d, const void* s) {
    asm volatile("cp.async.cg.shared.global [%0], [%1], 16;"
                 :: "r"(d), "l"(s) : "memory");
}
__device__ __forceinline__ void cp_commit() {
    asm volatile("cp.async.commit_group;" ::: "memory");
}
template<int N> __device__ __forceinline__ void cp_wait() {
    asm volatile("cp.async.wait_group %0;" :: "n"(N) : "memory");
}
__device__ __forceinline__ uint4 ldsm4(unsigned a) {
    uint4 r;
    asm volatile("ldmatrix.sync.aligned.m8n8.x4.shared.b16 {%0,%1,%2,%3}, [%4];"
                 : "=r"(r.x), "=r"(r.y), "=r"(r.z), "=r"(r.w) : "r"(a));
    return r;
}
__device__ __forceinline__ void mma16816(float* c, const uint4& a,
                                         unsigned b0, unsigned b1) {
    asm volatile(
        "mma.sync.aligned.m16n8k16.row.col.f32.f16.f16.f32 "
        "{%0,%1,%2,%3},{%4,%5,%6,%7},{%8,%9},{%0,%1,%2,%3};"
        : "+f"(c[0]), "+f"(c[1]), "+f"(c[2]), "+f"(c[3])
        : "r"(a.x), "r"(a.y), "r"(a.z), "r"(a.w), "r"(b0), "r"(b1));
}
__device__ __forceinline__ unsigned short h16(float v) {
    return __half_as_ushort(__float2half_rn(v));
}
__device__ __forceinline__ unsigned pk2(float a, float b) {
    return (unsigned)h16(a) | ((unsigned)h16(b) << 16);
}

// ---------------------------------------------------------------------------
// Small kernels
// ---------------------------------------------------------------------------
__global__ void zero_cnt_kernel() {
    if (threadIdx.x < NEXP) g_cnt[threadIdx.x] = 0;
}

__global__ void gate_kernel(const float* __restrict__ x,
                            const float* __restrict__ Wg) {
    int gwarp = (blockIdx.x * blockDim.x + threadIdx.x) >> 5;
    int lane  = threadIdx.x & 31;
    if (gwarp >= T_TOK) return;
    int t = gwarp;
    const float* xr = x + (size_t)t * DMODEL;
    float acc[NEXP];
#pragma unroll
    for (int e = 0; e < NEXP; e++) acc[e] = 0.f;
    for (int d = lane; d < DMODEL; d += 32) {
        float xv = xr[d];
        const float* wr = Wg + d * NEXP;
#pragma unroll
        for (int e = 0; e < NEXP; e++) acc[e] += xv * wr[e];
    }
#pragma unroll
    for (int e = 0; e < NEXP; e++)
#pragma unroll
        for (int off = 16; off; off >>= 1)
            acc[e] += __shfl_xor_sync(0xFFFFFFFFu, acc[e], off);
    if (lane == 0) {
        int i0 = 0; float l0 = acc[0];
#pragma unroll
        for (int e = 1; e < NEXP; e++) if (acc[e] > l0) { l0 = acc[e]; i0 = e; }
        int i1 = -1; float l1 = -3.0e38f;
#pragma unroll
        for (int e = 0; e < NEXP; e++)
            if (e != i0 && acc[e] > l1) { l1 = acc[e]; i1 = e; }
        float w0 = 1.0f / (1.0f + expf(l1 - l0));
        float w1 = 1.0f - w0;
        int p0 = atomicAdd(&g_cnt[i0], 1);
        g_list[i0][p0] = t * 2 + 0; g_wt[i0][p0] = w0;
        int p1 = atomicAdd(&g_cnt[i1], 1);
        g_list[i1][p1] = t * 2 + 1; g_wt[i1][p1] = w1;
    }
}

__global__ void conv_x_kernel(const float* __restrict__ x) {
    size_t i = ((size_t)blockIdx.x * blockDim.x + threadIdx.x) * 4;
    float4 v = *(const float4*)(x + i);
    ushort4 h;
    h.x = h16(v.x); h.y = h16(v.y); h.z = h16(v.z); h.w = h16(v.w);
    *(ushort4*)(g_x_h + i) = h;
}

// transpose + fp16 convert: in [R][C] fp32 per expert -> out [C][R] fp16
// write side: each thread emits one 16B store (8 contiguous R-halves)
template<int WSEL>
__global__ void transp_conv_kernel(const float* __restrict__ in) {
    const int R = (WSEL == 0) ? DMODEL : DFF;
    const int C = (WSEL == 0) ? DFF : DMODEL;
    __half* oh = (WSEL == 0) ? g_w1_h : g_w2_h;
    __shared__ float t[64][33];
    size_t eb = (size_t)blockIdx.z * (size_t)R * C;
    int c0 = blockIdx.x * 32, r0 = blockIdx.y * 64;
    int tx = threadIdx.x, ty = threadIdx.y;
    for (int i = ty; i < 64; i += 8)
        t[i][tx] = in[eb + (size_t)(r0 + i) * C + c0 + tx];
    __syncthreads();
    int tid  = ty * 32 + tx;
    int orow = tid >> 3;           // 0..31 (C index)
    int rg   = (tid & 7) * 8;      // 0..56 (R group)
    uint4 v;
    v.x = pk2(t[rg + 0][orow], t[rg + 1][orow]);
    v.y = pk2(t[rg + 2][orow], t[rg + 3][orow]);
    v.z = pk2(t[rg + 4][orow], t[rg + 5][orow]);
    v.w = pk2(t[rg + 6][orow], t[rg + 7][orow]);
    *(uint4*)(oh + eb + (size_t)(c0 + orow) * R + r0 + rg) = v;
}

__global__ void combine_kernel(float* __restrict__ out) {
    const int VPR = DMODEL / 4;
    int i = blockIdx.x * blockDim.x + threadIdx.x;
    if (i >= T_TOK * VPR) return;
    int t = i / VPR, c = i % VPR;
    const float4* y4 = (const float4*)g_y;
    float4 a = y4[(size_t)(2 * t) * VPR + c];
    float4 b = y4[(size_t)(2 * t + 1) * VPR + c];
    float4 r;
    r.x = a.x + b.x; r.y = a.y + b.y; r.z = a.z + b.z; r.w = a.w + b.w;
    ((float4*)out)[i] = r;
}

// ---------------------------------------------------------------------------
// Grouped GEMM via mma.sync fp16 (fp32 acc), 4-stage cp.async pipeline.
// MODE 0: A=g_x_h, B=g_w1 -> h = relu(acc + b1) stored fp16
// MODE 1: A=g_h_h, B=g_w2 -> y = wt * (acc + b2) stored fp32
// ---------------------------------------------------------------------------
template<int KTOT, int NTOT, int MODE>
__global__ void __launch_bounds__(256, 1)
moe_gemm_kernel(const float* __restrict__ bias) {
    extern __shared__ __align__(128) char smem[];
    const int e   = blockIdx.z;
    const int cnt = g_cnt[e];
    const int mB  = blockIdx.y * BM;
    if (mB >= cnt) return;
    const int nB  = blockIdx.x * BN;
    const int tid = threadIdx.x;
    const int lane = tid & 31;
    const int wid  = tid >> 5;
    const int warp_m = wid & 3;     // 4 warps along M (32 rows each)
    const int warp_n = wid >> 2;    // 2 warps along N (64 cols each)
    const int NCH = KTOT / BK;

    const __half* Ah = (MODE == 0) ? g_x_h : g_h_h;
    const __half* Bh = (MODE == 0) ? g_w1_h : g_w2_h;

    const unsigned sbase = smem_u32(smem);

    const int crow = tid >> 1;
    const int cseg = (tid & 1) * 32;
    const char *pA, *pB;
    {
        int m = mB + crow;
        int ar = 0;
        if (m < cnt) { int s = g_list[e][m]; ar = (MODE == 0) ? (s >> 1) : s; }
        pA = (const char*)(Ah + (size_t)ar * KTOT) + cseg;
        size_t bo = (size_t)e * NTOT * KTOT + (size_t)(nB + crow) * KTOT;
        pB = (const char*)(Bh + bo) + cseg;
    }
    const unsigned cdst = crow * ROWB + cseg;

#define LOADC(s, c) do { \
        unsigned st_ = sbase + (s) * STAGE_BYTES + cdst; \
        size_t ko_ = (size_t)(c) * (BK * 2); \
        cp16(st_ + OFF_A,      pA + ko_); \
        cp16(st_ + OFF_A + 16, pA + ko_ + 16); \
        cp16(st_ + OFF_B,      pB + ko_); \
        cp16(st_ + OFF_B + 16, pB + ko_ + 16); \
    } while (0)

    unsigned aoff[2], boff[4];
#pragma unroll
    for (int mt = 0; mt < 2; mt++)
        aoff[mt] = (unsigned)(warp_m * 32 + mt * 16 + (lane & 15)) * ROWB
                 + (unsigned)((lane >> 4) * 8) * 2;
#pragma unroll
    for (int p = 0; p < 4; p++)
        boff[p] = (unsigned)(warp_n * 64 + p * 16 + ((lane >> 4) << 3) + (lane & 7)) * ROWB
                + (unsigned)(((lane >> 3) & 1) * 8) * 2;

    float acc[2][8][4];
#pragma unroll
    for (int i = 0; i < 2; i++)
#pragma unroll
        for (int j = 0; j < 8; j++)
#pragma unroll
            for (int q = 0; q < 4; q++) acc[i][j][q] = 0.f;

    // prologue: fill 3 of 4 stages
    LOADC(0, 0); cp_commit();
    LOADC(1, 1); cp_commit();
    LOADC(2, 2); cp_commit();

    for (int c = 0; c < NCH; c++) {
        if (c + 3 < NCH) { LOADC((c + 3) & 3, c + 3); cp_commit(); }
        int rem = NCH - 1 - c;
        if (rem >= 3)      cp_wait<3>();
        else if (rem == 2) cp_wait<2>();
        else if (rem == 1) cp_wait<1>();
        else               cp_wait<0>();
        __syncthreads();

        const unsigned st = sbase + (c & 3) * STAGE_BYTES;
#pragma unroll
        for (int ks = 0; ks < 2; ks++) {
            const unsigned ko = ks * 32;
            uint4 ah[2];
#pragma unroll
            for (int mt = 0; mt < 2; mt++)
                ah[mt] = ldsm4(st + OFF_A + aoff[mt] + ko);
            uint4 bh[4];
#pragma unroll
            for (int p = 0; p < 4; p++)
                bh[p] = ldsm4(st + OFF_B + boff[p] + ko);
#pragma unroll
            for (int mt = 0; mt < 2; mt++)
#pragma unroll
                for (int p = 0; p < 4; p++) {
                    mma16816(acc[mt][2 * p],     ah[mt], bh[p].x, bh[p].y);
                    mma16816(acc[mt][2 * p + 1], ah[mt], bh[p].z, bh[p].w);
                }
        }
        __syncthreads();
    }

    // ---------------- epilogue: acc -> smem fp32 -> global ----------------
    float* ep = (float*)smem;
    {
        int g = lane >> 2, q4 = lane & 3;
#pragma unroll
        for (int mt = 0; mt < 2; mt++) {
            int r0 = warp_m * 32 + mt * 16 + g;
#pragma unroll
            for (int nt = 0; nt < 8; nt++) {
                int cc = warp_n * 64 + nt * 8 + q4 * 2;
                *(float2*)&ep[(size_t)r0 * EPITCH + cc] =
                    make_float2(acc[mt][nt][0], acc[mt][nt][1]);
                *(float2*)&ep[(size_t)(r0 + 8) * EPITCH + cc] =
                    make_float2(acc[mt][nt][2], acc[mt][nt][3]);
            }
        }
    }
    __syncthreads();

    {
        int r = tid >> 1;
        int m = mB + r;
        if (m < cnt) {
            int slot = g_list[e][m];
            int c0 = (tid & 1) * 64;
            const float* row = ep + (size_t)r * EPITCH + c0;
            const float* bp = bias + (size_t)e * NTOT + nB + c0;
            if (MODE == 0) {
                __half* dh = g_h_h + (size_t)slot * NTOT + nB + c0;
#pragma unroll
                for (int g2 = 0; g2 < 8; g2++) {
                    ushort4 hv;
#pragma unroll
                    for (int j = 0; j < 8; j++) {
                        float v = fmaxf(row[g2 * 8 + j] + bp[g2 * 8 + j], 0.f);
                        ((unsigned short*)&hv)[j & 3] = h16(v);
                        if ((j & 3) == 3)
                            *(ushort4*)(dh + g2 * 8 + j - 3) = hv;
                    }
                }
            } else {
                float w = g_wt[e][m];
                float* dy = g_y + (size_t)slot * NTOT + nB + c0;
#pragma unroll
                for (int g2 = 0; g2 < 16; g2++) {
                    float4 v;
                    v.x = w * (row[g2 * 4 + 0] + bp[g2 * 4 + 0]);
                    v.y = w * (row[g2 * 4 + 1] + bp[g2 * 4 + 1]);
                    v.z = w * (row[g2 * 4 + 2] + bp[g2 * 4 + 2]);
                    v.w = w * (row[g2 * 4 + 3] + bp[g2 * 4 + 3]);
                    *(float4*)(dy + g2 * 4) = v;
                }
            }
        }
    }
}

// ---------------------------------------------------------------------------
// Launch — graph-capturable stream fork so weight prep overlaps gating/GEMM1
// ---------------------------------------------------------------------------
extern "C" void kernel_launch(void* const* d_in, const int* in_sizes, int n_in,
                              void* d_out, int out_size) {
    const float* x  = (const float*)d_in[0];
    const float* Wg = (const float*)d_in[1];
    const float* W1 = (const float*)d_in[2];
    const float* b1 = (const float*)d_in[3];
    const float* W2 = (const float*)d_in[4];
    const float* b2 = (const float*)d_in[5];
    float* out = (float*)d_out;

    static cudaStream_t s1 = nullptr, s2 = nullptr;
    static cudaEvent_t ev_root = nullptr, ev_w1 = nullptr, ev_w2 = nullptr;
    if (s1 == nullptr) {
        cudaStreamCreateWithFlags(&s1, cudaStreamNonBlocking);
        cudaStreamCreateWithFlags(&s2, cudaStreamNonBlocking);
        cudaEventCreateWithFlags(&ev_root, cudaEventDisableTiming);
        cudaEventCreateWithFlags(&ev_w1, cudaEventDisableTiming);
        cudaEventCreateWithFlags(&ev_w2, cudaEventDisableTiming);
        cudaFuncSetAttribute(moe_gemm_kernel<DMODEL, DFF, 0>,
                             cudaFuncAttributeMaxDynamicSharedMemorySize, SMEM_TOTAL);
        cudaFuncSetAttribute(moe_gemm_kernel<DFF, DMODEL, 1>,
                             cudaFuncAttributeMaxDynamicSharedMemorySize, SMEM_TOTAL);
    }

    dim3 tb(32, 8);

    // fork side branches off the (capture-origin) default stream
    cudaEventRecord(ev_root, 0);
    cudaStreamWaitEvent(s1, ev_root, 0);
    cudaStreamWaitEvent(s2, ev_root, 0);

    // side stream 1: W1 prep
    transp_conv_kernel<0><<<dim3(DFF / 32, DMODEL / 64, NEXP), tb, 0, s1>>>(W1);
    cudaEventRecord(ev_w1, s1);
    // side stream 2: W2 prep
    transp_conv_kernel<1><<<dim3(DMODEL / 32, DFF / 64, NEXP), tb, 0, s2>>>(W2);
    cudaEventRecord(ev_w2, s2);

    // main stream: gating + x convert
    zero_cnt_kernel<<<1, 32>>>();
    gate_kernel<<<T_TOK / 8, 256>>>(x, Wg);
    conv_x_kernel<<<(T_TOK * DMODEL) / 4 / 256, 256>>>(x);

    cudaStreamWaitEvent(0, ev_w1, 0);
    moe_gemm_kernel<DMODEL, DFF, 0>
        <<<dim3(DFF / BN, T_TOK / BM, NEXP), 256, SMEM_TOTAL>>>(b1);

    cudaStreamWaitEvent(0, ev_w2, 0);
    moe_gemm_kernel<DFF, DMODEL, 1>
        <<<dim3(DMODEL / BN, T_TOK / BM, NEXP), 256, SMEM_TOTAL>>>(b2);

    combine_kernel<<<(T_TOK * (DMODEL / 4) + 255) / 256, 256>>>(out);
}

// round 11
// speedup vs baseline: 1.0034x; 1.0034x over previous
#include <cuda_runtime.h>
#include <cuda_fp16.h>

#define T_TOK  4096
#define DMODEL 1024
#define DFF    4096
#define NEXP   8
#define NSLOT  (T_TOK * 2)

#define BM 128
#define BN 128
#define BK 32                       // K elems per chunk
#define ROWB 80                     // padded row pitch bytes (64B data + 16B pad)
#define MATB (128 * ROWB)           // 10240 bytes per matrix
#define OFF_A 0
#define OFF_B MATB
#define STAGE_BYTES (2 * MATB)      // 20480
#define NSTAGE 4
#define SMEM_TOTAL (NSTAGE * STAGE_BYTES)   // 81920 >= epilogue 67584
#define EPITCH 132                  // fp32 epilogue row pitch (words)

// ---------------------------------------------------------------------------
// Scratch
// ---------------------------------------------------------------------------
__device__ int   g_cnt[NEXP];
__device__ int   g_list[NEXP][T_TOK];
__device__ float g_wt[NEXP][T_TOK];
__device__ __half g_x_h[(size_t)T_TOK * DMODEL];
__device__ __half g_w1_h[(size_t)NEXP * DFF * DMODEL];   // transposed [e][f][d]
__device__ __half g_w2_h[(size_t)NEXP * DMODEL * DFF];   // transposed [e][d][f]
__device__ __half g_h_h[(size_t)NSLOT * DFF];
__device__ float g_y[(size_t)NSLOT * DMODEL];

// ---------------------------------------------------------------------------
// PTX helpers (sm_80-class PTX only; tcgen05 rejected on plain sm_103 target)
// ---------------------------------------------------------------------------
__device__ __forceinline__ unsigned smem_u32(const void* p) {
    unsigned a;
    asm("{ .reg .u64 t; cvta.to.shared.u64 t, %1; cvt.u32.u64 %0, t; }"
        : "=r"(a) : "l"(p));
    return a;
}
__device__ __forceinline__ void cp16(unsigned d, const void* s) {
    asm volatile("cp.async.cg.shared.global [%0], [%1], 16;"
                 :: "r"(d), "l"(s) : "memory");
}
__device__ __forceinline__ void cp_commit() {
    asm volatile("cp.async.commit_group;" ::: "memory");
}
template<int N> __device__ __forceinline__ void cp_wait() {
    asm volatile("cp.async.wait_group %0;" :: "n"(N) : "memory");
}
__device__ __forceinline__ uint4 ldsm4(unsigned a) {
    uint4 r;
    asm volatile("ldmatrix.sync.aligned.m8n8.x4.shared.b16 {%0,%1,%2,%3}, [%4];"
                 : "=r"(r.x), "=r"(r.y), "=r"(r.z), "=r"(r.w) : "r"(a));
    return r;
}
__device__ __forceinline__ void mma16816(float* c, const uint4& a,
                                         unsigned b0, unsigned b1) {
    asm volatile(
        "mma.sync.aligned.m16n8k16.row.col.f32.f16.f16.f32 "
        "{%0,%1,%2,%3},{%4,%5,%6,%7},{%8,%9},{%0,%1,%2,%3};"
        : "+f"(c[0]), "+f"(c[1]), "+f"(c[2]), "+f"(c[3])
        : "r"(a.x), "r"(a.y), "r"(a.z), "r"(a.w), "r"(b0), "r"(b1));
}
__device__ __forceinline__ unsigned short h16(float v) {
    return __half_as_ushort(__float2half_rn(v));
}
__device__ __forceinline__ unsigned pk2(float a, float b) {
    return (unsigned)h16(a) | ((unsigned)h16(b) << 16);
}

// ---------------------------------------------------------------------------
// Small kernels
// ---------------------------------------------------------------------------
__global__ void zero_cnt_kernel() {
    if (threadIdx.x < NEXP) g_cnt[threadIdx.x] = 0;
}

// gating + fp16 convert of x fused: one pass over x.
__global__ void gate_kernel(const float* __restrict__ x,
                            const float* __restrict__ Wg) {
    int gwarp = (blockIdx.x * blockDim.x + threadIdx.x) >> 5;
    int lane  = threadIdx.x & 31;
    if (gwarp >= T_TOK) return;
    int t = gwarp;
    const float* xr = x + (size_t)t * DMODEL;
    __half* xo = g_x_h + (size_t)t * DMODEL;
    float acc[NEXP];
#pragma unroll
    for (int e = 0; e < NEXP; e++) acc[e] = 0.f;
    for (int d = lane; d < DMODEL; d += 32) {
        float xv = xr[d];
        xo[d] = __ushort_as_half(h16(xv));
        const float* wr = Wg + d * NEXP;
#pragma unroll
        for (int e = 0; e < NEXP; e++) acc[e] += xv * wr[e];
    }
#pragma unroll
    for (int e = 0; e < NEXP; e++)
#pragma unroll
        for (int off = 16; off; off >>= 1)
            acc[e] += __shfl_xor_sync(0xFFFFFFFFu, acc[e], off);
    if (lane == 0) {
        int i0 = 0; float l0 = acc[0];
#pragma unroll
        for (int e = 1; e < NEXP; e++) if (acc[e] > l0) { l0 = acc[e]; i0 = e; }
        int i1 = -1; float l1 = -3.0e38f;
#pragma unroll
        for (int e = 0; e < NEXP; e++)
            if (e != i0 && acc[e] > l1) { l1 = acc[e]; i1 = e; }
        float w0 = 1.0f / (1.0f + expf(l1 - l0));
        float w1 = 1.0f - w0;
        int p0 = atomicAdd(&g_cnt[i0], 1);
        g_list[i0][p0] = t * 2 + 0; g_wt[i0][p0] = w0;
        int p1 = atomicAdd(&g_cnt[i1], 1);
        g_list[i1][p1] = t * 2 + 1; g_wt[i1][p1] = w1;
    }
}

// transpose + fp16 convert: in [R][C] fp32 per expert -> out [C][R] fp16
// write side: each thread emits one 16B store (8 contiguous R-halves)
template<int WSEL>
__global__ void transp_conv_kernel(const float* __restrict__ in) {
    const int R = (WSEL == 0) ? DMODEL : DFF;
    const int C = (WSEL == 0) ? DFF : DMODEL;
    __half* oh = (WSEL == 0) ? g_w1_h : g_w2_h;
    __shared__ float t[64][33];
    size_t eb = (size_t)blockIdx.z * (size_t)R * C;
    int c0 = blockIdx.x * 32, r0 = blockIdx.y * 64;
    int tx = threadIdx.x, ty = threadIdx.y;
    for (int i = ty; i < 64; i += 8)
        t[i][tx] = in[eb + (size_t)(r0 + i) * C + c0 + tx];
    __syncthreads();
    int tid  = ty * 32 + tx;
    int orow = tid >> 3;           // 0..31 (C index)
    int rg   = (tid & 7) * 8;      // 0..56 (R group)
    uint4 v;
    v.x = pk2(t[rg + 0][orow], t[rg + 1][orow]);
    v.y = pk2(t[rg + 2][orow], t[rg + 3][orow]);
    v.z = pk2(t[rg + 4][orow], t[rg + 5][orow]);
    v.w = pk2(t[rg + 6][orow], t[rg + 7][orow]);
    *(uint4*)(oh + eb + (size_t)(c0 + orow) * R + r0 + rg) = v;
}

__global__ void combine_kernel(float* __restrict__ out) {
    const int VPR = DMODEL / 4;
    int i = blockIdx.x * blockDim.x + threadIdx.x;
    if (i >= T_TOK * VPR) return;
    int t = i / VPR, c = i % VPR;
    const float4* y4 = (const float4*)g_y;
    float4 a = y4[(size_t)(2 * t) * VPR + c];
    float4 b = y4[(size_t)(2 * t + 1) * VPR + c];
    float4 r;
    r.x = a.x + b.x; r.y = a.y + b.y; r.z = a.z + b.z; r.w = a.w + b.w;
    ((float4*)out)[i] = r;
}

// ---------------------------------------------------------------------------
// Grouped GEMM via mma.sync fp16 (fp32 acc), 4-stage cp.async pipeline.
// MODE 0: A=g_x_h, B=g_w1 -> h = relu(acc + b1) stored fp16
// MODE 1: A=g_h_h, B=g_w2 -> y = wt * (acc + b2) stored fp32
// ---------------------------------------------------------------------------
template<int KTOT, int NTOT, int MODE>
__global__ void __launch_bounds__(256, 1)
moe_gemm_kernel(const float* __restrict__ bias) {
    extern __shared__ __align__(128) char smem[];
    const int e   = blockIdx.z;
    const int cnt = g_cnt[e];
    const int mB  = blockIdx.y * BM;
    if (mB >= cnt) return;
    const int nB  = blockIdx.x * BN;
    const int tid = threadIdx.x;
    const int lane = tid & 31;
    const int wid  = tid >> 5;
    const int warp_m = wid & 3;     // 4 warps along M (32 rows each)
    const int warp_n = wid >> 2;    // 2 warps along N (64 cols each)
    const int NCH = KTOT / BK;

    const __half* Ah = (MODE == 0) ? g_x_h : g_h_h;
    const __half* Bh = (MODE == 0) ? g_w1_h : g_w2_h;

    const unsigned sbase = smem_u32(smem);

    const int crow = tid >> 1;
    const int cseg = (tid & 1) * 32;
    const char *pA, *pB;
    {
        int m = mB + crow;
        int ar = 0;
        if (m < cnt) { int s = g_list[e][m]; ar = (MODE == 0) ? (s >> 1) : s; }
        pA = (const char*)(Ah + (size_t)ar * KTOT) + cseg;
        size_t bo = (size_t)e * NTOT * KTOT + (size_t)(nB + crow) * KTOT;
        pB = (const char*)(Bh + bo) + cseg;
    }
    const unsigned cdst = crow * ROWB + cseg;

#define LOADC(s, c) do { \
        unsigned st_ = sbase + (s) * STAGE_BYTES + cdst; \
        size_t ko_ = (size_t)(c) * (BK * 2); \
        cp16(st_ + OFF_A,      pA + ko_); \
        cp16(st_ + OFF_A + 16, pA + ko_ + 16); \
        cp16(st_ + OFF_B,      pB + ko_); \
        cp16(st_ + OFF_B + 16, pB + ko_ + 16); \
    } while (0)

    unsigned aoff[2], boff[4];
#pragma unroll
    for (int mt = 0; mt < 2; mt++)
        aoff[mt] = (unsigned)(warp_m * 32 + mt * 16 + (lane & 15)) * ROWB
                 + (unsigned)((lane >> 4) * 8) * 2;
#pragma unroll
    for (int p = 0; p < 4; p++)
        boff[p] = (unsigned)(warp_n * 64 + p * 16 + ((lane >> 4) << 3) + (lane & 7)) * ROWB
                + (unsigned)(((lane >> 3) & 1) * 8) * 2;

    float acc[2][8][4];
#pragma unroll
    for (int i = 0; i < 2; i++)
#pragma unroll
        for (int j = 0; j < 8; j++)
#pragma unroll
            for (int q = 0; q < 4; q++) acc[i][j][q] = 0.f;

    // prologue: fill 3 of 4 stages
    LOADC(0, 0); cp_commit();
    LOADC(1, 1); cp_commit();
    LOADC(2, 2); cp_commit();

    for (int c = 0; c < NCH; c++) {
        if (c + 3 < NCH) { LOADC((c + 3) & 3, c + 3); cp_commit(); }
        int rem = NCH - 1 - c;
        if (rem >= 3)      cp_wait<3>();
        else if (rem == 2) cp_wait<2>();
        else if (rem == 1) cp_wait<1>();
        else               cp_wait<0>();
        __syncthreads();

        const unsigned st = sbase + (c & 3) * STAGE_BYTES;
#pragma unroll
        for (int ks = 0; ks < 2; ks++) {
            const unsigned ko = ks * 32;
            uint4 ah[2];
#pragma unroll
            for (int mt = 0; mt < 2; mt++)
                ah[mt] = ldsm4(st + OFF_A + aoff[mt] + ko);
            uint4 bh[4];
#pragma unroll
            for (int p = 0; p < 4; p++)
                bh[p] = ldsm4(st + OFF_B + boff[p] + ko);
#pragma unroll
            for (int mt = 0; mt < 2; mt++)
#pragma unroll
                for (int p = 0; p < 4; p++) {
                    mma16816(acc[mt][2 * p],     ah[mt], bh[p].x, bh[p].y);
                    mma16816(acc[mt][2 * p + 1], ah[mt], bh[p].z, bh[p].w);
                }
        }
        __syncthreads();
    }

    // ---------------- epilogue: acc -> smem fp32 -> global ----------------
    float* ep = (float*)smem;
    {
        int g = lane >> 2, q4 = lane & 3;
#pragma unroll
        for (int mt = 0; mt < 2; mt++) {
            int r0 = warp_m * 32 + mt * 16 + g;
#pragma unroll
            for (int nt = 0; nt < 8; nt++) {
                int cc = warp_n * 64 + nt * 8 + q4 * 2;
                *(float2*)&ep[(size_t)r0 * EPITCH + cc] =
                    make_float2(acc[mt][nt][0], acc[mt][nt][1]);
                *(float2*)&ep[(size_t)(r0 + 8) * EPITCH + cc] =
                    make_float2(acc[mt][nt][2], acc[mt][nt][3]);
            }
        }
    }
    __syncthreads();

    {
        int r = tid >> 1;
        int m = mB + r;
        if (m < cnt) {
            int slot = g_list[e][m];
            int c0 = (tid & 1) * 64;
            const float* row = ep + (size_t)r * EPITCH + c0;
            const float* bp = bias + (size_t)e * NTOT + nB + c0;
            if (MODE == 0) {
                __half* dh = g_h_h + (size_t)slot * NTOT + nB + c0;
#pragma unroll
                for (int g2 = 0; g2 < 8; g2++) {
                    ushort4 hv;
#pragma unroll
                    for (int j = 0; j < 8; j++) {
                        float v = fmaxf(row[g2 * 8 + j] + bp[g2 * 8 + j], 0.f);
                        ((unsigned short*)&hv)[j & 3] = h16(v);
                        if ((j & 3) == 3)
                            *(ushort4*)(dh + g2 * 8 + j - 3) = hv;
                    }
                }
            } else {
                float w = g_wt[e][m];
                float* dy = g_y + (size_t)slot * NTOT + nB + c0;
#pragma unroll
                for (int g2 = 0; g2 < 16; g2++) {
                    float4 v;
                    v.x = w * (row[g2 * 4 + 0] + bp[g2 * 4 + 0]);
                    v.y = w * (row[g2 * 4 + 1] + bp[g2 * 4 + 1]);
                    v.z = w * (row[g2 * 4 + 2] + bp[g2 * 4 + 2]);
                    v.w = w * (row[g2 * 4 + 3] + bp[g2 * 4 + 3]);
                    *(float4*)(dy + g2 * 4) = v;
                }
            }
        }
    }
}

// ---------------------------------------------------------------------------
// Launch (all serial on the capture stream)
// ---------------------------------------------------------------------------
extern "C" void kernel_launch(void* const* d_in, const int* in_sizes, int n_in,
                              void* d_out, int out_size) {
    const float* x  = (const float*)d_in[0];
    const float* Wg = (const float*)d_in[1];
    const float* W1 = (const float*)d_in[2];
    const float* b1 = (const float*)d_in[3];
    const float* W2 = (const float*)d_in[4];
    const float* b2 = (const float*)d_in[5];
    float* out = (float*)d_out;

    cudaFuncSetAttribute(moe_gemm_kernel<DMODEL, DFF, 0>,
                         cudaFuncAttributeMaxDynamicSharedMemorySize, SMEM_TOTAL);
    cudaFuncSetAttribute(moe_gemm_kernel<DFF, DMODEL, 1>,
                         cudaFuncAttributeMaxDynamicSharedMemorySize, SMEM_TOTAL);

    zero_cnt_kernel<<<1, 32>>>();
    gate_kernel<<<T_TOK / 8, 256>>>(x, Wg);

    dim3 tb(32, 8);
    transp_conv_kernel<0><<<dim3(DFF / 32, DMODEL / 64, NEXP), tb>>>(W1);
    transp_conv_kernel<1><<<dim3(DMODEL / 32, DFF / 64, NEXP), tb>>>(W2);

    moe_gemm_kernel<DMODEL, DFF, 0>
        <<<dim3(DFF / BN, T_TOK / BM, NEXP), 256, SMEM_TOTAL>>>(b1);
    moe_gemm_kernel<DFF, DMODEL, 1>
        <<<dim3(DMODEL / BN, T_TOK / BM, NEXP), 256, SMEM_TOTAL>>>(b2);

    combine_kernel<<<(T_TOK * (DMODEL / 4) + 255) / 256, 256>>>(out);
}

// round 12
// speedup vs baseline: 1.0860x; 1.0824x over previous
#include <cuda_runtime.h>
#include <cuda_fp16.h>

#define T_TOK  4096
#define DMODEL 1024
#define DFF    4096
#define NEXP   8
#define NSLOT  (T_TOK * 2)

#define BM 128
#define BN 128
#define BK 32                       // K elems per chunk
#define ROWB 80                     // padded row pitch bytes (64B data + 16B pad)
#define MATB (128 * ROWB)           // 10240 bytes per matrix
#define OFF_A 0
#define OFF_B MATB
#define STAGE_BYTES (2 * MATB)      // 20480
#define SMEM_TOTAL 67584            // epilogue needs 128*132*4 = 67584
#define EPITCH 132                  // fp32 epilogue row pitch (words)

// ---------------------------------------------------------------------------
// Scratch
// ---------------------------------------------------------------------------
__device__ int   g_cnt[NEXP];
__device__ int   g_list[NEXP][T_TOK];
__device__ float g_wt[NEXP][T_TOK];
__device__ __half g_x_h[(size_t)T_TOK * DMODEL];
__device__ __half g_w1_h[(size_t)NEXP * DFF * DMODEL];   // transposed [e][f][d]
__device__ __half g_w2_h[(size_t)NEXP * DMODEL * DFF];   // transposed [e][d][f]
__device__ __half g_h_h[(size_t)NSLOT * DFF];
__device__ float g_y[(size_t)NSLOT * DMODEL];

// ---------------------------------------------------------------------------
// PTX helpers (sm_80-class PTX only; tcgen05 rejected on plain sm_103 target)
// ---------------------------------------------------------------------------
__device__ __forceinline__ unsigned smem_u32(const void* p) {
    unsigned a;
    asm("{ .reg .u64 t; cvta.to.shared.u64 t, %1; cvt.u32.u64 %0, t; }"
        : "=r"(a) : "l"(p));
    return a;
}
__device__ __forceinline__ void cp16(unsigned d, const void* s) {
    asm volatile("cp.async.cg.shared.global [%0], [%1], 16;"
                 :: "r"(d), "l"(s) : "memory");
}
__device__ __forceinline__ void cp_commit() {
    asm volatile("cp.async.commit_group;" ::: "memory");
}
template<int N> __device__ __forceinline__ void cp_wait() {
    asm volatile("cp.async.wait_group %0;" :: "n"(N) : "memory");
}
__device__ __forceinline__ uint4 ldsm4(unsigned a) {
    uint4 r;
    asm volatile("ldmatrix.sync.aligned.m8n8.x4.shared.b16 {%0,%1,%2,%3}, [%4];"
                 : "=r"(r.x), "=r"(r.y), "=r"(r.z), "=r"(r.w) : "r"(a));
    return r;
}
__device__ __forceinline__ void mma16816(float* c, const uint4& a,
                                         unsigned b0, unsigned b1) {
    asm volatile(
        "mma.sync.aligned.m16n8k16.row.col.f32.f16.f16.f32 "
        "{%0,%1,%2,%3},{%4,%5,%6,%7},{%8,%9},{%0,%1,%2,%3};"
        : "+f"(c[0]), "+f"(c[1]), "+f"(c[2]), "+f"(c[3])
        : "r"(a.x), "r"(a.y), "r"(a.z), "r"(a.w), "r"(b0), "r"(b1));
}
__device__ __forceinline__ unsigned short h16(float v) {
    return __half_as_ushort(__float2half_rn(v));
}
__device__ __forceinline__ unsigned pk2(float a, float b) {
    return (unsigned)h16(a) | ((unsigned)h16(b) << 16);
}

// ---------------------------------------------------------------------------
// Small kernels
// ---------------------------------------------------------------------------
__global__ void zero_cnt_kernel() {
    if (threadIdx.x < NEXP) g_cnt[threadIdx.x] = 0;
}

// gating + fp16 convert of x fused: one pass over x.
__global__ void gate_kernel(const float* __restrict__ x,
                            const float* __restrict__ Wg) {
    int gwarp = (blockIdx.x * blockDim.x + threadIdx.x) >> 5;
    int lane  = threadIdx.x & 31;
    if (gwarp >= T_TOK) return;
    int t = gwarp;
    const float* xr = x + (size_t)t * DMODEL;
    __half* xo = g_x_h + (size_t)t * DMODEL;
    float acc[NEXP];
#pragma unroll
    for (int e = 0; e < NEXP; e++) acc[e] = 0.f;
    for (int d = lane; d < DMODEL; d += 32) {
        float xv = xr[d];
        xo[d] = __ushort_as_half(h16(xv));
        const float* wr = Wg + d * NEXP;
#pragma unroll
        for (int e = 0; e < NEXP; e++) acc[e] += xv * wr[e];
    }
#pragma unroll
    for (int e = 0; e < NEXP; e++)
#pragma unroll
        for (int off = 16; off; off >>= 1)
            acc[e] += __shfl_xor_sync(0xFFFFFFFFu, acc[e], off);
    if (lane == 0) {
        int i0 = 0; float l0 = acc[0];
#pragma unroll
        for (int e = 1; e < NEXP; e++) if (acc[e] > l0) { l0 = acc[e]; i0 = e; }
        int i1 = -1; float l1 = -3.0e38f;
#pragma unroll
        for (int e = 0; e < NEXP; e++)
            if (e != i0 && acc[e] > l1) { l1 = acc[e]; i1 = e; }
        float w0 = 1.0f / (1.0f + expf(l1 - l0));
        float w1 = 1.0f - w0;
        int p0 = atomicAdd(&g_cnt[i0], 1);
        g_list[i0][p0] = t * 2 + 0; g_wt[i0][p0] = w0;
        int p1 = atomicAdd(&g_cnt[i1], 1);
        g_list[i1][p1] = t * 2 + 1; g_wt[i1][p1] = w1;
    }
}

// transpose + fp16 convert: in [R][C] fp32 per expert -> out [C][R] fp16
template<int WSEL>
__global__ void transp_conv_kernel(const float* __restrict__ in) {
    const int R = (WSEL == 0) ? DMODEL : DFF;
    const int C = (WSEL == 0) ? DFF : DMODEL;
    __half* oh = (WSEL == 0) ? g_w1_h : g_w2_h;
    __shared__ float t[64][33];
    size_t eb = (size_t)blockIdx.z * (size_t)R * C;
    int c0 = blockIdx.x * 32, r0 = blockIdx.y * 64;
    int tx = threadIdx.x, ty = threadIdx.y;
    for (int i = ty; i < 64; i += 8)
        t[i][tx] = in[eb + (size_t)(r0 + i) * C + c0 + tx];
    __syncthreads();
    int tid  = ty * 32 + tx;
    int orow = tid >> 3;           // 0..31 (C index)
    int rg   = (tid & 7) * 8;      // 0..56 (R group)
    uint4 v;
    v.x = pk2(t[rg + 0][orow], t[rg + 1][orow]);
    v.y = pk2(t[rg + 2][orow], t[rg + 3][orow]);
    v.z = pk2(t[rg + 4][orow], t[rg + 5][orow]);
    v.w = pk2(t[rg + 6][orow], t[rg + 7][orow]);
    *(uint4*)(oh + eb + (size_t)(c0 + orow) * R + r0 + rg) = v;
}

__global__ void combine_kernel(float* __restrict__ out) {
    const int VPR = DMODEL / 4;
    int i = blockIdx.x * blockDim.x + threadIdx.x;
    if (i >= T_TOK * VPR) return;
    int t = i / VPR, c = i % VPR;
    const float4* y4 = (const float4*)g_y;
    float4 a = y4[(size_t)(2 * t) * VPR + c];
    float4 b = y4[(size_t)(2 * t + 1) * VPR + c];
    float4 r;
    r.x = a.x + b.x; r.y = a.y + b.y; r.z = a.z + b.z; r.w = a.w + b.w;
    ((float4*)out)[i] = r;
}

// ---------------------------------------------------------------------------
// Grouped GEMM via mma.sync fp16 (fp32 acc), 2-stage cp.async pipeline
// (exact R9 structure — the fastest measured config).
// MODE 0: A=g_x_h, B=g_w1 -> h = relu(acc + b1) stored fp16
// MODE 1: A=g_h_h, B=g_w2 -> y = wt * (acc + b2) stored fp32
// ---------------------------------------------------------------------------
template<int KTOT, int NTOT, int MODE>
__global__ void __launch_bounds__(256, 1)
moe_gemm_kernel(const float* __restrict__ bias) {
    extern __shared__ __align__(128) char smem[];
    const int e   = blockIdx.z;
    const int cnt = g_cnt[e];
    const int mB  = blockIdx.y * BM;
    if (mB >= cnt) return;
    const int nB  = blockIdx.x * BN;
    const int tid = threadIdx.x;
    const int lane = tid & 31;
    const int wid  = tid >> 5;
    const int warp_m = wid & 3;     // 4 warps along M (32 rows each)
    const int warp_n = wid >> 2;    // 2 warps along N (64 cols each)
    const int NCH = KTOT / BK;

    const __half* Ah = (MODE == 0) ? g_x_h : g_h_h;
    const __half* Bh = (MODE == 0) ? g_w1_h : g_w2_h;

    const unsigned sbase = smem_u32(smem);

    const int crow = tid >> 1;
    const int cseg = (tid & 1) * 32;
    const char *pA, *pB;
    {
        int m = mB + crow;
        int ar = 0;
        if (m < cnt) { int s = g_list[e][m]; ar = (MODE == 0) ? (s >> 1) : s; }
        pA = (const char*)(Ah + (size_t)ar * KTOT) + cseg;
        size_t bo = (size_t)e * NTOT * KTOT + (size_t)(nB + crow) * KTOT;
        pB = (const char*)(Bh + bo) + cseg;
    }
    const unsigned cdst = crow * ROWB + cseg;

#define LOADC(s, c) do { \
        unsigned st_ = sbase + (s) * STAGE_BYTES + cdst; \
        size_t ko_ = (size_t)(c) * (BK * 2); \
        cp16(st_ + OFF_A,      pA + ko_); \
        cp16(st_ + OFF_A + 16, pA + ko_ + 16); \
        cp16(st_ + OFF_B,      pB + ko_); \
        cp16(st_ + OFF_B + 16, pB + ko_ + 16); \
    } while (0)

    unsigned aoff[2], boff[4];
#pragma unroll
    for (int mt = 0; mt < 2; mt++)
        aoff[mt] = (unsigned)(warp_m * 32 + mt * 16 + (lane & 15)) * ROWB
                 + (unsigned)((lane >> 4) * 8) * 2;
#pragma unroll
    for (int p = 0; p < 4; p++)
        boff[p] = (unsigned)(warp_n * 64 + p * 16 + ((lane >> 4) << 3) + (lane & 7)) * ROWB
                + (unsigned)(((lane >> 3) & 1) * 8) * 2;

    float acc[2][8][4];
#pragma unroll
    for (int i = 0; i < 2; i++)
#pragma unroll
        for (int j = 0; j < 8; j++)
#pragma unroll
            for (int q = 0; q < 4; q++) acc[i][j][q] = 0.f;

    LOADC(0, 0);
    cp_commit();

    for (int c = 0; c < NCH; c++) {
        if (c + 1 < NCH) {
            LOADC((c + 1) & 1, c + 1);
            cp_commit();
            cp_wait<1>();
        } else {
            cp_wait<0>();
        }
        __syncthreads();

        const unsigned st = sbase + (c & 1) * STAGE_BYTES;
#pragma unroll
        for (int ks = 0; ks < 2; ks++) {
            const unsigned ko = ks * 32;
            uint4 ah[2];
#pragma unroll
            for (int mt = 0; mt < 2; mt++)
                ah[mt] = ldsm4(st + OFF_A + aoff[mt] + ko);
            uint4 bh[4];
#pragma unroll
            for (int p = 0; p < 4; p++)
                bh[p] = ldsm4(st + OFF_B + boff[p] + ko);
#pragma unroll
            for (int mt = 0; mt < 2; mt++)
#pragma unroll
                for (int p = 0; p < 4; p++) {
                    mma16816(acc[mt][2 * p],     ah[mt], bh[p].x, bh[p].y);
                    mma16816(acc[mt][2 * p + 1], ah[mt], bh[p].z, bh[p].w);
                }
        }
        __syncthreads();
    }

    // ---------------- epilogue: acc -> smem fp32 -> global ----------------
    float* ep = (float*)smem;
    {
        int g = lane >> 2, q4 = lane & 3;
#pragma unroll
        for (int mt = 0; mt < 2; mt++) {
            int r0 = warp_m * 32 + mt * 16 + g;
#pragma unroll
            for (int nt = 0; nt < 8; nt++) {
                int cc = warp_n * 64 + nt * 8 + q4 * 2;
                *(float2*)&ep[(size_t)r0 * EPITCH + cc] =
                    make_float2(acc[mt][nt][0], acc[mt][nt][1]);
                *(float2*)&ep[(size_t)(r0 + 8) * EPITCH + cc] =
                    make_float2(acc[mt][nt][2], acc[mt][nt][3]);
            }
        }
    }
    __syncthreads();

    {
        int r = tid >> 1;
        int m = mB + r;
        if (m < cnt) {
            int slot = g_list[e][m];
            int c0 = (tid & 1) * 64;
            const float* row = ep + (size_t)r * EPITCH + c0;
            const float* bp = bias + (size_t)e * NTOT + nB + c0;
            if (MODE == 0) {
                __half* dh = g_h_h + (size_t)slot * NTOT + nB + c0;
#pragma unroll
                for (int g2 = 0; g2 < 8; g2++) {
                    ushort4 hv;
#pragma unroll
                    for (int j = 0; j < 8; j++) {
                        float v = fmaxf(row[g2 * 8 + j] + bp[g2 * 8 + j], 0.f);
                        ((unsigned short*)&hv)[j & 3] = h16(v);
                        if ((j & 3) == 3)
                            *(ushort4*)(dh + g2 * 8 + j - 3) = hv;
                    }
                }
            } else {
                float w = g_wt[e][m];
                float* dy = g_y + (size_t)slot * NTOT + nB + c0;
#pragma unroll
                for (int g2 = 0; g2 < 16; g2++) {
                    float4 v;
                    v.x = w * (row[g2 * 4 + 0] + bp[g2 * 4 + 0]);
                    v.y = w * (row[g2 * 4 + 1] + bp[g2 * 4 + 1]);
                    v.z = w * (row[g2 * 4 + 2] + bp[g2 * 4 + 2]);
                    v.w = w * (row[g2 * 4 + 3] + bp[g2 * 4 + 3]);
                    *(float4*)(dy + g2 * 4) = v;
                }
            }
        }
    }
}

// ---------------------------------------------------------------------------
// Launch — W2 transpose forked to overlap GEMM1 (fork overhead measured ~3us)
// ---------------------------------------------------------------------------
extern "C" void kernel_launch(void* const* d_in, const int* in_sizes, int n_in,
                              void* d_out, int out_size) {
    const float* x  = (const float*)d_in[0];
    const float* Wg = (const float*)d_in[1];
    const float* W1 = (const float*)d_in[2];
    const float* b1 = (const float*)d_in[3];
    const float* W2 = (const float*)d_in[4];
    const float* b2 = (const float*)d_in[5];
    float* out = (float*)d_out;

    static cudaStream_t s2 = nullptr;
    static cudaEvent_t ev_fork = nullptr, ev_w2 = nullptr;
    if (s2 == nullptr) {
        cudaStreamCreateWithFlags(&s2, cudaStreamNonBlocking);
        cudaEventCreateWithFlags(&ev_fork, cudaEventDisableTiming);
        cudaEventCreateWithFlags(&ev_w2, cudaEventDisableTiming);
        cudaFuncSetAttribute(moe_gemm_kernel<DMODEL, DFF, 0>,
                             cudaFuncAttributeMaxDynamicSharedMemorySize, SMEM_TOTAL);
        cudaFuncSetAttribute(moe_gemm_kernel<DFF, DMODEL, 1>,
                             cudaFuncAttributeMaxDynamicSharedMemorySize, SMEM_TOTAL);
    }

    dim3 tb(32, 8);

    zero_cnt_kernel<<<1, 32>>>();
    gate_kernel<<<T_TOK / 8, 256>>>(x, Wg);
    transp_conv_kernel<0><<<dim3(DFF / 32, DMODEL / 64, NEXP), tb>>>(W1);

    // fork: W2 prep runs concurrent with GEMM1 (GEMM1 barely touches DRAM)
    cudaEventRecord(ev_fork, 0);
    cudaStreamWaitEvent(s2, ev_fork, 0);
    transp_conv_kernel<1><<<dim3(DMODEL / 32, DFF / 64, NEXP), tb, 0, s2>>>(W2);
    cudaEventRecord(ev_w2, s2);

    moe_gemm_kernel<DMODEL, DFF, 0>
        <<<dim3(DFF / BN, T_TOK / BM, NEXP), 256, SMEM_TOTAL>>>(b1);

    cudaStreamWaitEvent(0, ev_w2, 0);
    moe_gemm_kernel<DFF, DMODEL, 1>
        <<<dim3(DMODEL / BN, T_TOK / BM, NEXP), 256, SMEM_TOTAL>>>(b2);

    combine_kernel<<<(T_TOK * (DMODEL / 4) + 255) / 256, 256>>>(out);
}

// round 13
// speedup vs baseline: 1.0990x; 1.0119x over previous
#include <cuda_runtime.h>
#include <cuda_fp16.h>

#define T_TOK  4096
#define DMODEL 1024
#define DFF    4096
#define NEXP   8
#define NSLOT  (T_TOK * 2)

#define BM 128
#define BN 128
#define BK 32                       // K elems per chunk
#define ROWB 80                     // padded row pitch bytes (64B data + 16B pad)
#define MATB (128 * ROWB)           // 10240 bytes per matrix
#define OFF_A 0
#define OFF_B MATB
#define STAGE_BYTES (2 * MATB)      // 20480
#define SMEM_TOTAL 67584            // epilogue needs 128*132*4 = 67584
#define EPITCH 132                  // fp32 epilogue row pitch (words)

// ---------------------------------------------------------------------------
// Scratch
// ---------------------------------------------------------------------------
__device__ int   g_cnt[NEXP];
__device__ int   g_list[NEXP][T_TOK];
__device__ float g_wt[NEXP][T_TOK];
__device__ __half g_x_h[(size_t)T_TOK * DMODEL];
__device__ __half g_w1_h[(size_t)NEXP * DFF * DMODEL];   // transposed [e][f][d]
__device__ __half g_w2_h[(size_t)NEXP * DMODEL * DFF];   // transposed [e][d][f]
__device__ __half g_h_h[(size_t)NSLOT * DFF];
__device__ float g_y[(size_t)NSLOT * DMODEL];

// ---------------------------------------------------------------------------
// PTX helpers (sm_80-class PTX only; tcgen05 rejected on plain sm_103 target)
// ---------------------------------------------------------------------------
__device__ __forceinline__ unsigned smem_u32(const void* p) {
    unsigned a;
    asm("{ .reg .u64 t; cvta.to.shared.u64 t, %1; cvt.u32.u64 %0, t; }"
        : "=r"(a) : "l"(p));
    return a;
}
__device__ __forceinline__ void cp16(unsigned d, const void* s) {
    asm volatile("cp.async.cg.shared.global [%0], [%1], 16;"
                 :: "r"(d), "l"(s) : "memory");
}
__device__ __forceinline__ void cp_commit() {
    asm volatile("cp.async.commit_group;" ::: "memory");
}
template<int N> __device__ __forceinline__ void cp_wait() {
    asm volatile("cp.async.wait_group %0;" :: "n"(N) : "memory");
}
__device__ __forceinline__ uint4 ldsm4(unsigned a) {
    uint4 r;
    asm volatile("ldmatrix.sync.aligned.m8n8.x4.shared.b16 {%0,%1,%2,%3}, [%4];"
                 : "=r"(r.x), "=r"(r.y), "=r"(r.z), "=r"(r.w) : "r"(a));
    return r;
}
__device__ __forceinline__ void mma16816(float* c, const uint4& a,
                                         unsigned b0, unsigned b1) {
    asm volatile(
        "mma.sync.aligned.m16n8k16.row.col.f32.f16.f16.f32 "
        "{%0,%1,%2,%3},{%4,%5,%6,%7},{%8,%9},{%0,%1,%2,%3};"
        : "+f"(c[0]), "+f"(c[1]), "+f"(c[2]), "+f"(c[3])
        : "r"(a.x), "r"(a.y), "r"(a.z), "r"(a.w), "r"(b0), "r"(b1));
}
__device__ __forceinline__ unsigned short h16(float v) {
    return __half_as_ushort(__float2half_rn(v));
}
__device__ __forceinline__ unsigned pk2(float a, float b) {
    return (unsigned)h16(a) | ((unsigned)h16(b) << 16);
}

// ---------------------------------------------------------------------------
// Small kernels
// ---------------------------------------------------------------------------
__global__ void zero_cnt_kernel() {
    if (threadIdx.x < NEXP) g_cnt[threadIdx.x] = 0;
}

// gating + fp16 convert of x fused: one pass over x.
__global__ void gate_kernel(const float* __restrict__ x,
                            const float* __restrict__ Wg) {
    int gwarp = (blockIdx.x * blockDim.x + threadIdx.x) >> 5;
    int lane  = threadIdx.x & 31;
    if (gwarp >= T_TOK) return;
    int t = gwarp;
    const float* xr = x + (size_t)t * DMODEL;
    __half* xo = g_x_h + (size_t)t * DMODEL;
    float acc[NEXP];
#pragma unroll
    for (int e = 0; e < NEXP; e++) acc[e] = 0.f;
    for (int d = lane; d < DMODEL; d += 32) {
        float xv = xr[d];
        xo[d] = __ushort_as_half(h16(xv));
        const float* wr = Wg + d * NEXP;
#pragma unroll
        for (int e = 0; e < NEXP; e++) acc[e] += xv * wr[e];
    }
#pragma unroll
    for (int e = 0; e < NEXP; e++)
#pragma unroll
        for (int off = 16; off; off >>= 1)
            acc[e] += __shfl_xor_sync(0xFFFFFFFFu, acc[e], off);
    if (lane == 0) {
        int i0 = 0; float l0 = acc[0];
#pragma unroll
        for (int e = 1; e < NEXP; e++) if (acc[e] > l0) { l0 = acc[e]; i0 = e; }
        int i1 = -1; float l1 = -3.0e38f;
#pragma unroll
        for (int e = 0; e < NEXP; e++)
            if (e != i0 && acc[e] > l1) { l1 = acc[e]; i1 = e; }
        float w0 = 1.0f / (1.0f + expf(l1 - l0));
        float w1 = 1.0f - w0;
        int p0 = atomicAdd(&g_cnt[i0], 1);
        g_list[i0][p0] = t * 2 + 0; g_wt[i0][p0] = w0;
        int p1 = atomicAdd(&g_cnt[i1], 1);
        g_list[i1][p1] = t * 2 + 1; g_wt[i1][p1] = w1;
    }
}

// transpose + fp16 convert: in [R][C] fp32 per expert -> out [C][R] fp16
template<int WSEL>
__global__ void transp_conv_kernel(const float* __restrict__ in) {
    const int R = (WSEL == 0) ? DMODEL : DFF;
    const int C = (WSEL == 0) ? DFF : DMODEL;
    __half* oh = (WSEL == 0) ? g_w1_h : g_w2_h;
    __shared__ float t[64][33];
    size_t eb = (size_t)blockIdx.z * (size_t)R * C;
    int c0 = blockIdx.x * 32, r0 = blockIdx.y * 64;
    int tx = threadIdx.x, ty = threadIdx.y;
    for (int i = ty; i < 64; i += 8)
        t[i][tx] = in[eb + (size_t)(r0 + i) * C + c0 + tx];
    __syncthreads();
    int tid  = ty * 32 + tx;
    int orow = tid >> 3;           // 0..31 (C index)
    int rg   = (tid & 7) * 8;      // 0..56 (R group)
    uint4 v;
    v.x = pk2(t[rg + 0][orow], t[rg + 1][orow]);
    v.y = pk2(t[rg + 2][orow], t[rg + 3][orow]);
    v.z = pk2(t[rg + 4][orow], t[rg + 5][orow]);
    v.w = pk2(t[rg + 6][orow], t[rg + 7][orow]);
    *(uint4*)(oh + eb + (size_t)(c0 + orow) * R + r0 + rg) = v;
}

__global__ void combine_kernel(float* __restrict__ out) {
    const int VPR = DMODEL / 4;
    int i = blockIdx.x * blockDim.x + threadIdx.x;
    if (i >= T_TOK * VPR) return;
    int t = i / VPR, c = i % VPR;
    const float4* y4 = (const float4*)g_y;
    float4 a = y4[(size_t)(2 * t) * VPR + c];
    float4 b = y4[(size_t)(2 * t + 1) * VPR + c];
    float4 r;
    r.x = a.x + b.x; r.y = a.y + b.y; r.z = a.z + b.z; r.w = a.w + b.w;
    ((float4*)out)[i] = r;
}

// ---------------------------------------------------------------------------
// Grouped GEMM via mma.sync fp16 (fp32 acc), 2-stage cp.async pipeline.
// MODE 0: A=g_x_h, B=g_w1 -> h = relu(acc + b1) stored fp16
// MODE 1: A=g_h_h, B=g_w2 -> y = wt * (acc + b2) stored fp32
// ---------------------------------------------------------------------------
template<int KTOT, int NTOT, int MODE>
__global__ void __launch_bounds__(256, 1)
moe_gemm_kernel(const float* __restrict__ bias) {
    extern __shared__ __align__(128) char smem[];
    const int e   = blockIdx.z;
    const int cnt = g_cnt[e];
    const int mB  = blockIdx.y * BM;
    if (mB >= cnt) return;
    const int nB  = blockIdx.x * BN;
    const int tid = threadIdx.x;
    const int lane = tid & 31;
    const int wid  = tid >> 5;
    const int warp_m = wid & 3;     // 4 warps along M (32 rows each)
    const int warp_n = wid >> 2;    // 2 warps along N (64 cols each)
    const int NCH = KTOT / BK;

    const __half* Ah = (MODE == 0) ? g_x_h : g_h_h;
    const __half* Bh = (MODE == 0) ? g_w1_h : g_w2_h;

    const unsigned sbase = smem_u32(smem);

    const int crow = tid >> 1;
    const int cseg = (tid & 1) * 32;
    const char *pA, *pB;
    {
        int m = mB + crow;
        int ar = 0;
        if (m < cnt) { int s = g_list[e][m]; ar = (MODE == 0) ? (s >> 1) : s; }
        pA = (const char*)(Ah + (size_t)ar * KTOT) + cseg;
        size_t bo = (size_t)e * NTOT * KTOT + (size_t)(nB + crow) * KTOT;
        pB = (const char*)(Bh + bo) + cseg;
    }
    const unsigned cdst = crow * ROWB + cseg;

#define LOADC(s, c) do { \
        unsigned st_ = sbase + (s) * STAGE_BYTES + cdst; \
        size_t ko_ = (size_t)(c) * (BK * 2); \
        cp16(st_ + OFF_A,      pA + ko_); \
        cp16(st_ + OFF_A + 16, pA + ko_ + 16); \
        cp16(st_ + OFF_B,      pB + ko_); \
        cp16(st_ + OFF_B + 16, pB + ko_ + 16); \
    } while (0)

    unsigned aoff[2], boff[4];
#pragma unroll
    for (int mt = 0; mt < 2; mt++)
        aoff[mt] = (unsigned)(warp_m * 32 + mt * 16 + (lane & 15)) * ROWB
                 + (unsigned)((lane >> 4) * 8) * 2;
#pragma unroll
    for (int p = 0; p < 4; p++)
        boff[p] = (unsigned)(warp_n * 64 + p * 16 + ((lane >> 4) << 3) + (lane & 7)) * ROWB
                + (unsigned)(((lane >> 3) & 1) * 8) * 2;

    float acc[2][8][4];
#pragma unroll
    for (int i = 0; i < 2; i++)
#pragma unroll
        for (int j = 0; j < 8; j++)
#pragma unroll
            for (int q = 0; q < 4; q++) acc[i][j][q] = 0.f;

    LOADC(0, 0);
    cp_commit();

    for (int c = 0; c < NCH; c++) {
        if (c + 1 < NCH) {
            LOADC((c + 1) & 1, c + 1);
            cp_commit();
            cp_wait<1>();
        } else {
            cp_wait<0>();
        }
        __syncthreads();

        const unsigned st = sbase + (c & 1) * STAGE_BYTES;
#pragma unroll
        for (int ks = 0; ks < 2; ks++) {
            const unsigned ko = ks * 32;
            uint4 ah[2];
#pragma unroll
            for (int mt = 0; mt < 2; mt++)
                ah[mt] = ldsm4(st + OFF_A + aoff[mt] + ko);
            uint4 bh[4];
#pragma unroll
            for (int p = 0; p < 4; p++)
                bh[p] = ldsm4(st + OFF_B + boff[p] + ko);
#pragma unroll
            for (int mt = 0; mt < 2; mt++)
#pragma unroll
                for (int p = 0; p < 4; p++) {
                    mma16816(acc[mt][2 * p],     ah[mt], bh[p].x, bh[p].y);
                    mma16816(acc[mt][2 * p + 1], ah[mt], bh[p].z, bh[p].w);
                }
        }
        __syncthreads();
    }

    // ---------------- epilogue: acc -> smem fp32 -> global ----------------
    float* ep = (float*)smem;
    {
        int g = lane >> 2, q4 = lane & 3;
#pragma unroll
        for (int mt = 0; mt < 2; mt++) {
            int r0 = warp_m * 32 + mt * 16 + g;
#pragma unroll
            for (int nt = 0; nt < 8; nt++) {
                int cc = warp_n * 64 + nt * 8 + q4 * 2;
                *(float2*)&ep[(size_t)r0 * EPITCH + cc] =
                    make_float2(acc[mt][nt][0], acc[mt][nt][1]);
                *(float2*)&ep[(size_t)(r0 + 8) * EPITCH + cc] =
                    make_float2(acc[mt][nt][2], acc[mt][nt][3]);
            }
        }
    }
    __syncthreads();

    {
        int r = tid >> 1;
        int m = mB + r;
        if (m < cnt) {
            int slot = g_list[e][m];
            int c0 = (tid & 1) * 64;
            const float* row = ep + (size_t)r * EPITCH + c0;
            const float* bp = bias + (size_t)e * NTOT + nB + c0;
            if (MODE == 0) {
                __half* dh = g_h_h + (size_t)slot * NTOT + nB + c0;
#pragma unroll
                for (int g2 = 0; g2 < 8; g2++) {
                    ushort4 hv;
#pragma unroll
                    for (int j = 0; j < 8; j++) {
                        float v = fmaxf(row[g2 * 8 + j] + bp[g2 * 8 + j], 0.f);
                        ((unsigned short*)&hv)[j & 3] = h16(v);
                        if ((j & 3) == 3)
                            *(ushort4*)(dh + g2 * 8 + j - 3) = hv;
                    }
                }
            } else {
                float w = g_wt[e][m];
                float* dy = g_y + (size_t)slot * NTOT + nB + c0;
#pragma unroll
                for (int g2 = 0; g2 < 16; g2++) {
                    float4 v;
                    v.x = w * (row[g2 * 4 + 0] + bp[g2 * 4 + 0]);
                    v.y = w * (row[g2 * 4 + 1] + bp[g2 * 4 + 1]);
                    v.z = w * (row[g2 * 4 + 2] + bp[g2 * 4 + 2]);
                    v.w = w * (row[g2 * 4 + 3] + bp[g2 * 4 + 3]);
                    *(float4*)(dy + g2 * 4) = v;
                }
            }
        }
    }
}

// ---------------------------------------------------------------------------
// Launch — both weight transposes forked; transp1 overlaps gating,
// transp2 overlaps GEMM1 (fork overhead measured ~3us in R10/R11).
// ---------------------------------------------------------------------------
extern "C" void kernel_launch(void* const* d_in, const int* in_sizes, int n_in,
                              void* d_out, int out_size) {
    const float* x  = (const float*)d_in[0];
    const float* Wg = (const float*)d_in[1];
    const float* W1 = (const float*)d_in[2];
    const float* b1 = (const float*)d_in[3];
    const float* W2 = (const float*)d_in[4];
    const float* b2 = (const float*)d_in[5];
    float* out = (float*)d_out;

    static cudaStream_t s2 = nullptr;
    static cudaEvent_t ev_fork = nullptr, ev_w1 = nullptr, ev_w2 = nullptr;
    if (s2 == nullptr) {
        cudaStreamCreateWithFlags(&s2, cudaStreamNonBlocking);
        cudaEventCreateWithFlags(&ev_fork, cudaEventDisableTiming);
        cudaEventCreateWithFlags(&ev_w1, cudaEventDisableTiming);
        cudaEventCreateWithFlags(&ev_w2, cudaEventDisableTiming);
        cudaFuncSetAttribute(moe_gemm_kernel<DMODEL, DFF, 0>,
                             cudaFuncAttributeMaxDynamicSharedMemorySize, SMEM_TOTAL);
        cudaFuncSetAttribute(moe_gemm_kernel<DFF, DMODEL, 1>,
                             cudaFuncAttributeMaxDynamicSharedMemorySize, SMEM_TOTAL);
    }

    dim3 tb(32, 8);

    // fork both weight transposes immediately
    cudaEventRecord(ev_fork, 0);
    cudaStreamWaitEvent(s2, ev_fork, 0);
    transp_conv_kernel<0><<<dim3(DFF / 32, DMODEL / 64, NEXP), tb, 0, s2>>>(W1);
    cudaEventRecord(ev_w1, s2);
    transp_conv_kernel<1><<<dim3(DMODEL / 32, DFF / 64, NEXP), tb, 0, s2>>>(W2);
    cudaEventRecord(ev_w2, s2);

    // main stream: gating (fused x convert)
    zero_cnt_kernel<<<1, 32>>>();
    gate_kernel<<<T_TOK / 8, 256>>>(x, Wg);

    cudaStreamWaitEvent(0, ev_w1, 0);
    moe_gemm_kernel<DMODEL, DFF, 0>
        <<<dim3(DFF / BN, T_TOK / BM, NEXP), 256, SMEM_TOTAL>>>(b1);

    cudaStreamWaitEvent(0, ev_w2, 0);
    moe_gemm_kernel<DFF, DMODEL, 1>
        <<<dim3(DMODEL / BN, T_TOK / BM, NEXP), 256, SMEM_TOTAL>>>(b2);

    combine_kernel<<<(T_TOK * (DMODEL / 4) + 255) / 256, 256>>>(out);
}